// round 9
// baseline (speedup 1.0000x reference)
#include <cuda_runtime.h>

#define B_ROWS   65536
#define NPAIRS   (B_ROWS / 2)
#define KPOS     6
#define KNEG     30
#define NTARG    36
#define NGRAMS   12
#define D2       25      // EMBED=50 floats = 25 float2

#define GRID     740     // 5 blocks/SM * 148 SMs
#define TPB      256
#define WPB      (TPB / 32)
#define NWARPS   (GRID * WPB)

__device__ float g_partial[GRID];
__device__ int   g_ticket = 0;

__device__ __forceinline__ float softplusf(float x) {
    return fmaxf(x, 0.0f) + __logf(1.0f + __expf(-fabsf(x)));
}

__global__ void __launch_bounds__(TPB, 5)
fasttext_fused(const int* __restrict__ input_labels,
               const int* __restrict__ pos_labels,
               const int* __restrict__ neg_labels,
               const int* __restrict__ trigram_idx,
               const int* __restrict__ ngram_mask,
               const float2* __restrict__ cW,
               const float2* __restrict__ bW,
               const float2* __restrict__ tW,
               float* __restrict__ out)
{
    const int lane = threadIdx.x & 31;
    const int warp = threadIdx.x >> 5;
    const int gw   = blockIdx.x * WPB + warp;
    const unsigned FULL = 0xFFFFFFFFu;

    const int half = lane >> 4;          // 0 = row A, 1 = row B
    const int hl   = lane & 15;          // lane within half
    const int hbase = half << 4;         // shfl source base for this half
    const bool a1 = (hl < 13);           // holds elements hl
    const bool a2 = (hl < 12);           // holds elements 13+hl

    float lacc = 0.0f;                   // per-lane; 4x-replicated per target

    for (int pr = gw; pr < NPAIRS; pr += NWARPS) {
        const int row = 2 * pr + half;

        // ---- per-half lane-distributed index loads ----
        const int ci    = input_labels[row];                       // uniform per half
        const int pidx  = (hl < KPOS)      ? pos_labels[row * KPOS + hl]        : 0;
        const int nidx0 = neg_labels[row * KNEG + hl];             // hl < 16 <= 30
        const int nidx1 = (hl < KNEG - 16) ? neg_labels[row * KNEG + 16 + hl]   : 0;
        int tpack = -1;
        if (hl < NGRAMS) {
            int ti = trigram_idx[row * NGRAMS + hl];
            int mk = ngram_mask[row * NGRAMS + hl];
            tpack = mk ? ti : -1;
        }

        // ---- context vector m: lane holds float2 elems {hl, 13+hl} ----
        float2 m1 = make_float2(0.f, 0.f), m2 = make_float2(0.f, 0.f);
        if (a1) m1 = cW[ci * D2 + hl];
        if (a2) m2 = cW[ci * D2 + 13 + hl];
        #pragma unroll
        for (int n = 0; n < NGRAMS; n++) {
            int ti = __shfl_sync(FULL, tpack, hbase | n);   // per-half broadcast
            if (ti >= 0) {
                if (a1) { float2 t = tW[ti * D2 + hl];      m1.x += t.x; m1.y += t.y; }
                if (a2) { float2 t = tW[ti * D2 + 13 + hl]; m2.x += t.x; m2.y += t.y; }
            }
        }

        // ---- 36 dots in 9 groups of 4, 16-lane packed butterfly ----
        #pragma unroll
        for (int g = 0; g < 9; g++) {
            float p[4];
            #pragma unroll
            for (int j = 0; j < 4; j++) {
                const int t = 4 * g + j;                    // compile-time
                int ti;
                if (t < KPOS)            ti = __shfl_sync(FULL, pidx,  hbase | t);
                else if (t < KPOS + 16)  ti = __shfl_sync(FULL, nidx0, hbase | (t - KPOS));
                else                     ti = __shfl_sync(FULL, nidx1, hbase | (t - KPOS - 16));
                float pp = 0.f;
                if (a1) { float2 e = bW[ti * D2 + hl];      pp = fmaf(m1.x, e.x, m1.y * e.y); }
                if (a2) { float2 e = bW[ti * D2 + 13 + hl]; pp = fmaf(m2.x, e.x, fmaf(m2.y, e.y, pp)); }
                p[j] = pp;
            }
            // redundant stages: every lane keeps its (hl mod 4)-class partial
            #pragma unroll
            for (int j = 0; j < 4; j++) {
                p[j] += __shfl_xor_sync(FULL, p[j], 8);
                p[j] += __shfl_xor_sync(FULL, p[j], 4);
            }
            const int q = (lane >> 2) & 3;                  // this lane's target in group
            float v = (q == 0) ? p[0] : (q == 1) ? p[1] : (q == 2) ? p[2] : p[3];
            v += __shfl_xor_sync(FULL, v, 2);
            v += __shfl_xor_sync(FULL, v, 1);
            // v = full score of target 4g+q (this half's row), replicated 4x
            float x;
            if (4 * g + 3 < KPOS)      x = -v;                      // all-positive group
            else if (4 * g >= KPOS)    x = v;                       // all-negative group
            else                       x = (q < KPOS - 4 * g) ? -v : v;
            lacc += softplusf(x);
        }
    }

    lacc *= 0.25f;   // each target was accumulated on 4 lanes

    // ---- warp reduce (sums both halves' rows) ----
    lacc += __shfl_xor_sync(FULL, lacc, 16);
    lacc += __shfl_xor_sync(FULL, lacc, 8);
    lacc += __shfl_xor_sync(FULL, lacc, 4);
    lacc += __shfl_xor_sync(FULL, lacc, 2);
    lacc += __shfl_xor_sync(FULL, lacc, 1);

    __shared__ float sred[WPB];
    __shared__ int   slast;
    if (lane == 0) sred[warp] = lacc;
    __syncthreads();
    if (threadIdx.x == 0) {
        float s = 0.f;
        #pragma unroll
        for (int i = 0; i < WPB; i++) s += sred[i];
        g_partial[blockIdx.x] = s;
        __threadfence();
        int t = atomicAdd(&g_ticket, 1);
        slast = (t == GRID - 1) ? 1 : 0;
    }
    __syncthreads();

    // ---- last block: deterministic final reduction ----
    if (slast) {
        __threadfence();
        float s = 0.f;
        for (int i = threadIdx.x; i < GRID; i += TPB) s += g_partial[i];
        s += __shfl_xor_sync(FULL, s, 16);
        s += __shfl_xor_sync(FULL, s, 8);
        s += __shfl_xor_sync(FULL, s, 4);
        s += __shfl_xor_sync(FULL, s, 2);
        s += __shfl_xor_sync(FULL, s, 1);
        __shared__ float fred[WPB];
        if (lane == 0) fred[warp] = s;
        __syncthreads();
        if (threadIdx.x == 0) {
            float tot = 0.f;
            #pragma unroll
            for (int i = 0; i < WPB; i++) tot += fred[i];
            out[0] = tot;
            g_ticket = 0;   // reset for next graph replay
        }
    }
}

extern "C" void kernel_launch(void* const* d_in, const int* in_sizes, int n_in,
                              void* d_out, int out_size)
{
    const int*    input_labels = (const int*)d_in[0];
    const int*    pos_labels   = (const int*)d_in[1];
    const int*    neg_labels   = (const int*)d_in[2];
    const int*    trigram_idx  = (const int*)d_in[3];
    const int*    ngram_mask   = (const int*)d_in[4];
    const float2* cW           = (const float2*)d_in[5];
    const float2* bW           = (const float2*)d_in[6];
    const float2* tW           = (const float2*)d_in[7];

    fasttext_fused<<<GRID, TPB>>>(input_labels, pos_labels, neg_labels,
                                  trigram_idx, ngram_mask, cW, bW, tW,
                                  (float*)d_out);
}